// round 9
// baseline (speedup 1.0000x reference)
#include <cuda_runtime.h>
#include <cstdint>

#define NN 8192
#define DD 64
#define EPSF 1e-6f
#define PITCH_W 36   // words per Z smem row (144B): conflict-free frag loads
#define T_U 0.0625f  // log1p poly valid below this (abs err < 4e-6)

// scratch (no allocations allowed)
__device__ double g_acc;
__device__ float g_pi[NN];    // sq_i + 2*eps*s_i + D*eps^2   (EXACT fp32)
__device__ float g_qa[NN*2];  // interleaved: (sq_j - 2*eps*s_j, alpha_j)

// ---------------------------------------------------------------------------
__global__ void prep_kernel(const float* __restrict__ Z,
                            const float* __restrict__ alpha) {
    if (blockIdx.x == 0 && threadIdx.x == 0) g_acc = 0.0;
    int w = (blockIdx.x * blockDim.x + threadIdx.x) >> 5;
    int lane = threadIdx.x & 31;
    if (w >= NN) return;
    float2 v = ((const float2*)(Z + (size_t)w * DD))[lane];
    float s = v.x + v.y;
    float sq = v.x * v.x + v.y * v.y;
#pragma unroll
    for (int off = 16; off; off >>= 1) {
        s  += __shfl_xor_sync(0xffffffffu, s, off);
        sq += __shfl_xor_sync(0xffffffffu, sq, off);
    }
    if (lane == 0) {
        g_pi[w] = sq + 2.0f * EPSF * s + (float)DD * EPSF * EPSF;
        g_qa[2 * w]     = sq - 2.0f * EPSF * s;
        g_qa[2 * w + 1] = alpha[w];
    }
}

__device__ __forceinline__ uint32_t pack_bf16x2(float lo, float hi) {
    uint32_t r;  // first cvt source -> upper half
    asm("cvt.rn.bf16x2.f32 %0, %1, %2;" : "=r"(r) : "f"(hi), "f"(lo));
    return r;
}

__device__ __forceinline__ float sqrt_approx(float x) {
    float r;
    asm("sqrt.approx.f32 %0, %1;" : "=f"(r) : "f"(x));
    return r;
}

__device__ __forceinline__ float log1p_poly(float u) {
    return u * fmaf(u, fmaf(u, 0.33333333f, -0.5f), 1.0f);
}

// ---------------------------------------------------------------------------
// main: symmetric-pair bf16 gram. Block (bi<=bj) covers 128x128 unordered
// pairs; 256 threads, 8 warps in 4(row)x2(col) layout, warp tile 32x64.
// One gram + one sqrt per pair; both orientations via direct coalesced LDGs.
// ---------------------------------------------------------------------------
// smem byte offsets
#define SM_ZI   0                       // 128*36 words = 18432 B
#define SM_ZJ   18432                   // 18432 B
#define SM_PI   36864                   // 128 floats
#define SM_AI   37376                   // 128 floats (alpha_i)
#define SM_QA   37888                   // 128 float2
#define SM_WS   38912                   // 8 floats
#define SM_TOT  38944

__global__ __launch_bounds__(256) void lsm_main(const int* __restrict__ A,
                                                const float* __restrict__ Z) {
    const int bi = blockIdx.y, bj = blockIdx.x;   // I-block, J-block
    if (bi > bj) return;
    extern __shared__ __align__(16) char smem[];
    uint32_t* s_zi = (uint32_t*)(smem + SM_ZI);
    uint32_t* s_zj = (uint32_t*)(smem + SM_ZJ);
    float* s_pi = (float*)(smem + SM_PI);
    float* s_ai = (float*)(smem + SM_AI);
    float2* s_qa = (float2*)(smem + SM_QA);
    float* s_ws = (float*)(smem + SM_WS);

    const int tid = (int)threadIdx.x;
    const int wid = tid >> 5, lane = tid & 31;
    const int g = lane >> 2, t = lane & 3;
    const int wm = (wid & 3) * 32;      // warp row base (0..96)
    const int wc = (wid >> 2) * 64;     // warp col base (0 or 64)
    const bool diagblk = (bi == bj);

    // ---- small arrays ----
    if (tid < 128) {
        s_pi[tid] = g_pi[bi * 128 + tid];
        s_ai[tid] = g_qa[2 * (bi * 128 + tid) + 1];
        s_qa[tid] = ((const float2*)g_qa)[bj * 128 + tid];
    }

    // ---- Z tiles (bf16) ----
    {
        const float4* src = (const float4*)(Z + (size_t)(bi * 128) * DD);
#pragma unroll
        for (int it = 0; it < 8; ++it) {
            int idx = it * 256 + tid;      // 2048 float4s
            int r = idx >> 4, k4 = idx & 15;
            float4 v = src[(size_t)r * 16 + k4];
            *(uint2*)(s_zi + r * PITCH_W + k4 * 2) =
                make_uint2(pack_bf16x2(v.x, v.y), pack_bf16x2(v.z, v.w));
        }
        const float4* srcj = (const float4*)(Z + (size_t)(bj * 128) * DD);
#pragma unroll
        for (int it = 0; it < 8; ++it) {
            int idx = it * 256 + tid;
            int r = idx >> 4, k4 = idx & 15;
            float4 v = srcj[(size_t)r * 16 + k4];
            *(uint2*)(s_zj + r * PITCH_W + k4 * 2) =
                make_uint2(pack_bf16x2(v.x, v.y), pack_bf16x2(v.z, v.w));
        }
    }
    __syncthreads();

    // ---- a-fragments (K=64 -> 4 k16-steps, 2 m-frags) ----
    uint32_t a[4][2][4];
#pragma unroll
    for (int ks = 0; ks < 4; ++ks) {
#pragma unroll
        for (int mf = 0; mf < 2; ++mf) {
            int r0 = wm + mf * 16 + g;
            const uint32_t* base = s_zi + ks * 8 + t;
            a[ks][mf][0] = base[r0 * PITCH_W];
            a[ks][mf][1] = base[(r0 + 8) * PITCH_W];
            a[ks][mf][2] = base[r0 * PITCH_W + 4];
            a[ks][mf][3] = base[(r0 + 8) * PITCH_W + 4];
        }
    }

    // per-thread row constants + A_ij row pointers
    float pir[4], air[4];
    const int2* ar[4];
#pragma unroll
    for (int mf = 0; mf < 2; ++mf)
#pragma unroll
        for (int rs = 0; rs < 2; ++rs) {
            int r = mf * 2 + rs;
            int i_loc = wm + mf * 16 + rs * 8 + g;
            pir[r] = s_pi[i_loc];
            air[r] = s_ai[i_loc];
            ar[r] = (const int2*)(A + (size_t)(bi * 128 + i_loc) * NN + bj * 128);
        }

    float ll = 0.0f;
    float acc0[2][4], acc1[2][4];

#define DO_MMA(NF, ACC)                                                        \
    do {                                                                       \
        _Pragma("unroll")                                                      \
        for (int mf = 0; mf < 2; ++mf)                                         \
            _Pragma("unroll")                                                  \
            for (int e = 0; e < 4; ++e) ACC[mf][e] = 0.0f;                     \
        _Pragma("unroll")                                                      \
        for (int ks = 0; ks < 4; ++ks) {                                       \
            int c0 = wc + (NF) * 8 + g;                                        \
            uint32_t b0 = s_zj[c0 * PITCH_W + ks * 8 + t];                     \
            uint32_t b1 = s_zj[c0 * PITCH_W + ks * 8 + t + 4];                 \
            _Pragma("unroll")                                                  \
            for (int mf = 0; mf < 2; ++mf) {                                   \
                asm volatile(                                                  \
                    "mma.sync.aligned.m16n8k16.row.col.f32.bf16.bf16.f32 "     \
                    "{%0,%1,%2,%3}, {%4,%5,%6,%7}, {%8,%9}, {%0,%1,%2,%3};"    \
                    : "+f"(ACC[mf][0]), "+f"(ACC[mf][1]),                      \
                      "+f"(ACC[mf][2]), "+f"(ACC[mf][3])                       \
                    : "r"(a[ks][mf][0]), "r"(a[ks][mf][1]),                    \
                      "r"(a[ks][mf][2]), "r"(a[ks][mf][3]),                    \
                      "r"(b0), "r"(b1));                                       \
            }                                                                  \
        }                                                                      \
    } while (0)

#define DO_EPI(NF, ACC)                                                        \
    do {                                                                       \
        float uu[16];                                                          \
        bool slow = false;                                                     \
        int jb = wc + (NF) * 8 + 2 * t;                                        \
        float2 qa0 = s_qa[jb];                                                 \
        float2 qa1 = s_qa[jb + 1];                                             \
        _Pragma("unroll")                                                      \
        for (int mf = 0; mf < 2; ++mf)                                         \
            _Pragma("unroll")                                                  \
            for (int rs = 0; rs < 2; ++rs) {                                   \
                int r = mf * 2 + rs;                                           \
                int i_loc = wm + mf * 16 + rs * 8 + g;                         \
                int ig = bi * 128 + i_loc;                                     \
                int2 a2 = ar[r][wc / 2 + (NF) * 4 + t];                        \
                _Pragma("unroll")                                              \
                for (int c = 0; c < 2; ++c) {                                  \
                    int e = r * 2 + c;                                         \
                    int jt = jb + c;                                           \
                    int jg = bj * 128 + jt;                                    \
                    int aji = A[(size_t)jg * NN + ig];                         \
                    int aij = c ? a2.y : a2.x;                                 \
                    float2 q = c ? qa1 : qa0;                                  \
                    bool valid = !diagblk || (i_loc < jt);                     \
                    float d2 = fmaf(-2.0f, ACC[mf][rs * 2 + c],                \
                                    pir[r] + q.x);                             \
                    float zd = sqrt_approx(fmaxf(d2, 0.0f));                   \
                    float tha = q.y - zd;                                      \
                    float thb = air[r] - zd;                                   \
                    float ua = __expf(tha);                                    \
                    float ub = __expf(thb);                                    \
                    if (!valid) { ua = 0.0f; ub = 0.0f; }                      \
                    uu[e] = ua; uu[e + 8] = ub;                                \
                    slow = slow || (ua > T_U) || (ub > T_U);                   \
                    float cb = -(log1p_poly(ua) + log1p_poly(ub));             \
                    if (valid && aij) cb += tha;                               \
                    if (valid && aji) cb += thb;                               \
                    if (valid) ll += cb;                                       \
                }                                                              \
            }                                                                  \
        if (__any_sync(0xffffffffu, slow)) {                                   \
            _Pragma("unroll")                                                  \
            for (int e = 0; e < 16; ++e)                                       \
                if (uu[e] > T_U)                                               \
                    ll += log1p_poly(uu[e]) - __logf(1.0f + uu[e]);            \
        }                                                                      \
    } while (0)

    // ---- skewed pipeline: MMA(nf) overlaps epilogue(nf-1) ----
    DO_MMA(0, acc0);
    DO_MMA(1, acc1);  DO_EPI(0, acc0);
    DO_MMA(2, acc0);  DO_EPI(1, acc1);
    DO_MMA(3, acc1);  DO_EPI(2, acc0);
    DO_MMA(4, acc0);  DO_EPI(3, acc1);
    DO_MMA(5, acc1);  DO_EPI(4, acc0);
    DO_MMA(6, acc0);  DO_EPI(5, acc1);
    DO_MMA(7, acc1);  DO_EPI(6, acc0);
    DO_EPI(7, acc1);

    ll *= 0.5f;

    // ---- reduce + single double atomic per block ----
#pragma unroll
    for (int off = 16; off; off >>= 1) ll += __shfl_xor_sync(0xffffffffu, ll, off);
    if (lane == 0) s_ws[wid] = ll;
    __syncthreads();
    if (tid == 0) {
        float b = 0.0f;
#pragma unroll
        for (int w = 0; w < 8; ++w) b += s_ws[w];
        atomicAdd(&g_acc, (double)b);
    }
}

// ---------------------------------------------------------------------------
// finish: add analytic diagonal term 0.5 * sum_i A_ii * (alpha_i - sqrt(D)*eps)
// and emit the final scalar.
// ---------------------------------------------------------------------------
__global__ void finish_kernel(const int* __restrict__ A, float* out) {
    __shared__ float sh[8];
    int tid = (int)threadIdx.x;
    float p = 0.0f;
    for (int i = tid; i < NN; i += 256)
        if (A[(size_t)i * NN + i]) p += g_qa[2 * i + 1] - 8.0f * EPSF;
#pragma unroll
    for (int off = 16; off; off >>= 1) p += __shfl_xor_sync(0xffffffffu, p, off);
    if ((tid & 31) == 0) sh[tid >> 5] = p;
    __syncthreads();
    if (tid == 0) {
        float d = 0.0f;
#pragma unroll
        for (int w = 0; w < 8; ++w) d += sh[w];
        out[0] = (float)(g_acc + 0.5 * (double)d);
    }
}

// ---------------------------------------------------------------------------
extern "C" void kernel_launch(void* const* d_in, const int* in_sizes, int n_in,
                              void* d_out, int out_size) {
    const int* A = nullptr;
    const float* alpha = nullptr;
    const float* Z = nullptr;
    for (int i = 0; i < n_in; ++i) {
        if (in_sizes[i] == NN) alpha = (const float*)d_in[i];
        else if (in_sizes[i] == NN * DD) Z = (const float*)d_in[i];
        else A = (const int*)d_in[i];
    }

    cudaFuncSetAttribute(lsm_main, cudaFuncAttributeMaxDynamicSharedMemorySize,
                         SM_TOT);

    prep_kernel<<<(NN * 32 + 255) / 256, 256>>>(Z, alpha);
    dim3 grid(NN / 128, NN / 128);
    lsm_main<<<grid, 256, SM_TOT>>>(A, Z);
    finish_kernel<<<1, 256>>>(A, (float*)d_out);
}

// round 11
// speedup vs baseline: 1.0970x; 1.0970x over previous
#include <cuda_runtime.h>
#include <cuda_fp16.h>
#include <cstdint>

#define NN 8192
#define DD 64
#define EPSF 1e-6f
#define PITCH_W 36   // 32-bit words per smem row (144B): conflict-free frags
#define T_U 0.0625f  // poly valid below this
#define L2E 1.44269504f
#define LN2 0.69314718f
#define POLY_TU 0.06062825f   // poly(T_U)

// scratch (no allocations allowed)
__device__ double g_acc;
__device__ float g_pi[NN];    // sq_i + 2*eps*s_i + D*eps^2   (EXACT fp32)
__device__ float g_qa[NN*2];  // interleaved: (sq_j - 2*eps*s_j, alpha_j*log2e)

// ---------------------------------------------------------------------------
__global__ void prep_kernel(const float* __restrict__ Z,
                            const float* __restrict__ alpha) {
    if (blockIdx.x == 0 && threadIdx.x == 0) g_acc = 0.0;
    int w = (blockIdx.x * blockDim.x + threadIdx.x) >> 5;
    int lane = threadIdx.x & 31;
    if (w >= NN) return;
    float2 v = ((const float2*)(Z + (size_t)w * DD))[lane];
    float s = v.x + v.y;
    float sq = v.x * v.x + v.y * v.y;
#pragma unroll
    for (int off = 16; off; off >>= 1) {
        s  += __shfl_xor_sync(0xffffffffu, s, off);
        sq += __shfl_xor_sync(0xffffffffu, sq, off);
    }
    if (lane == 0) {
        g_pi[w] = sq + 2.0f * EPSF * s + (float)DD * EPSF * EPSF;
        g_qa[2 * w]     = sq - 2.0f * EPSF * s;
        g_qa[2 * w + 1] = alpha[w] * L2E;     // alpha in log2 units
    }
}

__device__ __forceinline__ uint32_t pack_bf16x2(float lo, float hi) {
    uint32_t r;  // first cvt source -> upper half
    asm("cvt.rn.bf16x2.f32 %0, %1, %2;" : "=r"(r) : "f"(hi), "f"(lo));
    return r;
}

__device__ __forceinline__ float sqrt_approx(float x) {
    float r;
    asm("sqrt.approx.f32 %0, %1;" : "=f"(r) : "f"(x));
    return r;
}

__device__ __forceinline__ float ex2f(float x) {
    float r;
    asm("ex2.approx.f32 %0, %1;" : "=f"(r) : "f"(x));
    return r;
}

__device__ __forceinline__ float log1p_poly32(float u) {
    return u * fmaf(u, fmaf(u, 0.33333333f, -0.5f), 1.0f);
}

// ---------------------------------------------------------------------------
// main: bf16 mma.sync gram (tile 128 x 64, K=64) + packed-f16 epilogue.
// 128 threads (4 warps); warp tile 32(M) x 64(N); nf-outer skewed pipeline.
// ---------------------------------------------------------------------------
__global__ __launch_bounds__(128) void lsm_main(const int* __restrict__ A,
                                                const float* __restrict__ Z) {
    extern __shared__ __align__(16) uint32_t smem[];
    uint32_t* s_zi = smem;                       // [128][PITCH_W] bf16x2 words
    uint32_t* s_zj = smem + 128 * PITCH_W;       // [64][PITCH_W]
    float* s_pi = (float*)(s_zj + 64 * PITCH_W); // [128]
    float* s_qa = s_pi + 128;                    // 64 float2
    float* s_ws = s_qa + 128;                    // [4]

    const int tid = (int)threadIdx.x;
    const int wid = tid >> 5, lane = tid & 31;
    const int g = lane >> 2, t = lane & 3;
    const int bi = blockIdx.y, bj = blockIdx.x;   // rows bi*128, cols bj*64
    const int wm = wid * 32;
    const bool diagblk = ((bj >> 1) == bi);

    // ---- stage small arrays ----
    s_pi[tid] = g_pi[bi * 128 + tid];
    if (tid < 64) ((float2*)s_qa)[tid] = ((const float2*)g_qa)[bj * 64 + tid];

    // ---- stage Z tiles as bf16 (rn) ----
    {
        const float4* src = (const float4*)(Z + (size_t)(bi * 128) * DD);
#pragma unroll
        for (int it = 0; it < 16; ++it) {
            int idx = it * 128 + tid;
            int r = idx >> 4, k4 = idx & 15;
            float4 v = src[(size_t)r * 16 + k4];
            *(uint2*)(s_zi + r * PITCH_W + k4 * 2) =
                make_uint2(pack_bf16x2(v.x, v.y), pack_bf16x2(v.z, v.w));
        }
        const float4* srcj = (const float4*)(Z + (size_t)(bj * 64) * DD);
#pragma unroll
        for (int it = 0; it < 8; ++it) {
            int idx = it * 128 + tid;
            int r = idx >> 4, k4 = idx & 15;
            float4 v = srcj[(size_t)r * 16 + k4];
            *(uint2*)(s_zj + r * PITCH_W + k4 * 2) =
                make_uint2(pack_bf16x2(v.x, v.y), pack_bf16x2(v.z, v.w));
        }
    }
    __syncthreads();

    const float2* qaf2 = (const float2*)s_qa;

    // ---- preload ALL a-fragments (K=64 -> 4 k16-steps) ----
    uint32_t a[4][2][4];
#pragma unroll
    for (int ks = 0; ks < 4; ++ks) {
#pragma unroll
        for (int mf = 0; mf < 2; ++mf) {
            int r0 = wm + mf * 16 + g;
            const uint32_t* base = s_zi + ks * 8 + t;
            a[ks][mf][0] = base[r0 * PITCH_W];
            a[ks][mf][1] = base[(r0 + 8) * PITCH_W];
            a[ks][mf][2] = base[r0 * PITCH_W + 4];
            a[ks][mf][3] = base[(r0 + 8) * PITCH_W + 4];
        }
    }

    // per-thread row constants
    float pir[4];
    const int2* ar[4];
#pragma unroll
    for (int mf = 0; mf < 2; ++mf)
#pragma unroll
        for (int rs = 0; rs < 2; ++rs) {
            int r = mf * 2 + rs;
            int i_loc = wm + mf * 16 + rs * 8 + g;
            pir[r] = s_pi[i_loc];
            ar[r] = (const int2*)(A + (size_t)(bi * 128 + i_loc) * NN + bj * 64);
        }

    float llA = 0.0f;    // sum of A_ij * theta (log2 units)
    float llS = 0.0f;    // sum of softplus (natural units)
    float acc0[2][4], acc1[2][4];

    const __half2 H2_TU  = __float2half2_rn(T_U);
    const __half2 H2_C3  = __float2half2_rn(0.33333333f);
    const __half2 H2_CM5 = __float2half2_rn(-0.5f);
    const __half2 H2_ONE = __float2half2_rn(1.0f);

#define DO_MMA(NF, ACC)                                                        \
    do {                                                                       \
        _Pragma("unroll")                                                      \
        for (int mf = 0; mf < 2; ++mf)                                         \
            _Pragma("unroll")                                                  \
            for (int e = 0; e < 4; ++e) ACC[mf][e] = 0.0f;                     \
        _Pragma("unroll")                                                      \
        for (int ks = 0; ks < 4; ++ks) {                                       \
            int c0 = (NF) * 8 + g;                                             \
            uint32_t b0 = s_zj[c0 * PITCH_W + ks * 8 + t];                     \
            uint32_t b1 = s_zj[c0 * PITCH_W + ks * 8 + t + 4];                 \
            _Pragma("unroll")                                                  \
            for (int mf = 0; mf < 2; ++mf) {                                   \
                asm volatile(                                                  \
                    "mma.sync.aligned.m16n8k16.row.col.f32.bf16.bf16.f32 "     \
                    "{%0,%1,%2,%3}, {%4,%5,%6,%7}, {%8,%9}, {%0,%1,%2,%3};"    \
                    : "+f"(ACC[mf][0]), "+f"(ACC[mf][1]),                      \
                      "+f"(ACC[mf][2]), "+f"(ACC[mf][3])                       \
                    : "r"(a[ks][mf][0]), "r"(a[ks][mf][1]),                    \
                      "r"(a[ks][mf][2]), "r"(a[ks][mf][3]),                    \
                      "r"(b0), "r"(b1));                                       \
            }                                                                  \
        }                                                                      \
    } while (0)

#define DO_EPI(NF, ACC)                                                        \
    do {                                                                       \
        float tl[8];                                                           \
        __half2 accs = __float2half2_rn(0.0f);                                 \
        __half2 umax = __float2half2_rn(0.0f);                                 \
        float2 qa0 = qaf2[(NF) * 8 + 2 * t];                                   \
        float2 qa1 = qaf2[(NF) * 8 + 2 * t + 1];                               \
        _Pragma("unroll")                                                      \
        for (int mf = 0; mf < 2; ++mf)                                         \
            _Pragma("unroll")                                                  \
            for (int rs = 0; rs < 2; ++rs) {                                   \
                int r = mf * 2 + rs;                                           \
                int2 a2 = ar[r][(NF) * 4 + t];                                 \
                float d20 = fmaf(-2.0f, ACC[mf][rs * 2 + 0], pir[r] + qa0.x);  \
                float d21 = fmaf(-2.0f, ACC[mf][rs * 2 + 1], pir[r] + qa1.x);  \
                float zd0 = sqrt_approx(fmaxf(d20, 0.0f));                     \
                float zd1 = sqrt_approx(fmaxf(d21, 0.0f));                     \
                float thl0 = fmaf(zd0, -L2E, qa0.y);                           \
                float thl1 = fmaf(zd1, -L2E, qa1.y);                           \
                tl[r * 2] = thl0; tl[r * 2 + 1] = thl1;                        \
                if (a2.x) llA += thl0;                                         \
                if (a2.y) llA += thl1;                                         \
                uint32_t pk, ub;                                               \
                asm("cvt.rn.f16x2.f32 %0, %1, %2;"                             \
                    : "=r"(pk) : "f"(thl1), "f"(thl0));                        \
                asm("ex2.approx.f16x2 %0, %1;" : "=r"(ub) : "r"(pk));          \
                __half2 uh = *reinterpret_cast<__half2*>(&ub);                 \
                umax = __hmax2(umax, uh);                                      \
                __half2 uc = __hmin2(uh, H2_TU);                               \
                __half2 p1 = __hfma2(uc, H2_C3, H2_CM5);                       \
                __half2 p2 = __hfma2(uc, p1, H2_ONE);                          \
                accs = __hfma2(uc, p2, accs);                                  \
            }                                                                  \
        float2 fa = __half22float2(accs);                                      \
        llS += fa.x + fa.y;                                                    \
        float2 um = __half22float2(umax);                                      \
        if (um.x > T_U || um.y > T_U) {  /* rare */                            \
            _Pragma("unroll")                                                  \
            for (int e = 0; e < 8; ++e) {                                      \
                float u = ex2f(tl[e]);                                         \
                if (u > T_U) llS += __logf(1.0f + u) - POLY_TU;                \
            }                                                                  \
        }                                                                      \
        if (diagblk) {                                                         \
            _Pragma("unroll")                                                  \
            for (int mf = 0; mf < 2; ++mf)                                     \
                _Pragma("unroll")                                              \
                for (int rs = 0; rs < 2; ++rs)                                 \
                    _Pragma("unroll")                                          \
                    for (int c = 0; c < 2; ++c) {                              \
                        int i_loc = wm + mf * 16 + rs * 8 + g;                 \
                        int ig = bi * 128 + i_loc;                             \
                        int jg = bj * 64 + (NF) * 8 + 2 * t + c;               \
                        if (ig == jg) {                                        \
                            float u = ex2f(tl[(mf * 2 + rs) * 2 + c]);         \
                            /* subtract exactly what the main path added: */   \
                            /* u>T_U: clamped poly + slow corr = log(1+u)  */  \
                            llS -= (u > T_U) ? __logf(1.0f + u)                \
                                             : log1p_poly32(u);               \
                        }                                                      \
                    }                                                          \
        }                                                                      \
    } while (0)

    // ---- skewed pipeline: MMA(nf) overlaps epilogue(nf-1) ----
    DO_MMA(0, acc0);
    DO_MMA(1, acc1);  DO_EPI(0, acc0);
    DO_MMA(2, acc0);  DO_EPI(1, acc1);
    DO_MMA(3, acc1);  DO_EPI(2, acc0);
    DO_MMA(4, acc0);  DO_EPI(3, acc1);
    DO_MMA(5, acc1);  DO_EPI(4, acc0);
    DO_MMA(6, acc0);  DO_EPI(5, acc1);
    DO_MMA(7, acc1);  DO_EPI(6, acc0);
    DO_EPI(7, acc1);

    float ll = 0.5f * (fmaf(llA, LN2, -llS));

    // ---- reduce + single double atomic per block ----
#pragma unroll
    for (int off = 16; off; off >>= 1) ll += __shfl_xor_sync(0xffffffffu, ll, off);
    if (lane == 0) s_ws[wid] = ll;
    __syncthreads();
    if (tid == 0)
        atomicAdd(&g_acc, (double)(s_ws[0] + s_ws[1] + s_ws[2] + s_ws[3]));
}

__global__ void finish_kernel(float* out) { out[0] = (float)g_acc; }

// ---------------------------------------------------------------------------
extern "C" void kernel_launch(void* const* d_in, const int* in_sizes, int n_in,
                              void* d_out, int out_size) {
    const int* A = nullptr;
    const float* alpha = nullptr;
    const float* Z = nullptr;
    for (int i = 0; i < n_in; ++i) {
        if (in_sizes[i] == NN) alpha = (const float*)d_in[i];
        else if (in_sizes[i] == NN * DD) Z = (const float*)d_in[i];
        else A = (const int*)d_in[i];
    }

    const int smem_bytes = (128 * PITCH_W + 64 * PITCH_W + 128 + 128 + 4) * 4;
    cudaFuncSetAttribute(lsm_main, cudaFuncAttributeMaxDynamicSharedMemorySize,
                         smem_bytes);

    prep_kernel<<<(NN * 32 + 255) / 256, 256>>>(Z, alpha);
    dim3 grid(NN / 64, NN / 128);
    lsm_main<<<grid, 128, smem_bytes>>>(A, Z);
    finish_kernel<<<1, 1>>>((float*)d_out);
}